// round 14
// baseline (speedup 1.0000x reference)
#include <cuda_runtime.h>
#include <cuda_fp16.h>
#include <cstdint>

#define NN 50000
#define EE 1600000
#define CC 128
#define NG 128
#define SB 1024
#define NBK ((NN + SB - 1) / SB)   // 49

// ---- scratch (static device globals) ----
__device__ uint2  s_Hh [NN * 32];    // H  fp16: 128 halves/row
__device__ uint2  s_P0h[NN * 32];    // layer out fp16 (relu applied)
__device__ uint2  s_P1h[NN * 32];
__device__ __half s_W1h[CC * CC];
__device__ __half s_W2h[CC * CC];
__device__ float  s_dinv[NN];
__device__ int    s_deg [NN];
__device__ int    s_rowptr[NN + 1];
__device__ int    s_cursor[NN];
__device__ int    s_csrc [EE];
__device__ float  s_coef [EE];
__device__ int    s_pref [NBK];      // chained-scan prefixes (-1 = not ready)
__device__ float  s_gacc[NG];        // pooled dot accumulators

// ============ init: zero deg / sentinels / gacc + convert W (one kernel) ============
__global__ void init_k(const float* __restrict__ W1, const float* __restrict__ W2) {
    int i = blockIdx.x * blockDim.x + threadIdx.x;
    if (i < NN) s_deg[i] = 0;
    if (i < NBK) s_pref[i] = -1;
    if (i < NG) s_gacc[i] = 0.f;
    if (i < CC * CC) {
        s_W1h[i] = __float2half(W1[i]);
        s_W2h[i] = __float2half(W2[i]);
    }
}

__global__ void deg_k(const int* __restrict__ ei) {
    int e = blockIdx.x * blockDim.x + threadIdx.x;
    if (e < EE) {
        int dst = ei[EE + e];
        dst = min(max(dst, 0), NN - 1);
        atomicAdd(&s_deg[dst], 1);
    }
}

// ============ fused chained scan: rowptr/cursor/dinv in ONE kernel ============
__global__ void scanf_k() {
    const int tid  = threadIdx.x;
    const int lane = tid & 31;
    const int wid  = tid >> 5;
    const int bid  = blockIdx.x;
    const int i    = bid * SB + tid;
    int v = (i < NN) ? s_deg[i] : 0;

    int x = v;
    #pragma unroll
    for (int o = 1; o < 32; o <<= 1) {
        int t = __shfl_up_sync(0xffffffffu, x, o);
        if (lane >= o) x += t;
    }
    __shared__ int wsum[32];
    if (lane == 31) wsum[wid] = x;
    __syncthreads();
    if (wid == 0) {
        int s = wsum[lane];
        #pragma unroll
        for (int o = 1; o < 32; o <<= 1) {
            int t = __shfl_up_sync(0xffffffffu, s, o);
            if (lane >= o) s += t;
        }
        wsum[lane] = s;
    }
    __syncthreads();
    int incl  = x + (wid ? wsum[wid - 1] : 0);
    int total = wsum[31];

    __shared__ int sprev;
    if (tid == 0) {
        int prev = 0;
        if (bid > 0)
            while ((prev = atomicAdd(&s_pref[bid - 1], 0)) < 0) {}
        sprev = prev;
        __threadfence();
        atomicExch(&s_pref[bid], prev + total);
    }
    __syncthreads();
    int base = sprev;

    if (i < NN) {
        int ex = base + incl - v;
        s_rowptr[i] = ex;
        s_cursor[i] = ex;
        s_dinv[i]   = rsqrtf((float)s_deg[i] + 1.0f);
    }
    if (i == 0) s_rowptr[NN] = EE;
}

__global__ void build_k(const int* __restrict__ ei) {
    int e = blockIdx.x * blockDim.x + threadIdx.x;
    if (e >= EE) return;
    int src = ei[e];
    int dst = ei[EE + e];
    src = min(max(src, 0), NN - 1);
    dst = min(max(dst, 0), NN - 1);
    int slot = atomicAdd(&s_cursor[dst], 1);
    slot = min(max(slot, 0), EE - 1);
    s_csrc[slot] = src;
    s_coef[slot] = s_dinv[src] * s_dinv[dst];
}

// ============ tensor-core GEMM: H(fp16) = A @ W ============
__device__ __forceinline__ unsigned swz(unsigned row, unsigned col_half) {
    unsigned b = row * 256u + col_half * 2u;
    return b ^ ((row & 7u) << 4);
}

template<int SRC>
__global__ void __launch_bounds__(256) gemm_tc_k(const float* __restrict__ X,
                                                 const __half* __restrict__ Wh) {
    __shared__ __align__(16) unsigned char smem[49152];   // A: 16KB, W: 32KB
    const unsigned sb  = (unsigned)__cvta_generic_to_shared(smem);
    const unsigned sbA = sb;
    const unsigned sbW = sb + 16384u;
    const int tid  = threadIdx.x;
    const int row0 = blockIdx.x * 64;

    if (SRC == 0) {
        #pragma unroll
        for (int it = 0; it < 4; it++) {
            int idx = it * 256 + tid;
            int r   = idx >> 4;
            int c16 = idx & 15;
            int gr  = row0 + r;
            uint4 o;
            if (gr < NN) {
                const float4* p = (const float4*)(X + (size_t)gr * CC + c16 * 8);
                float4 f0 = p[0], f1 = p[1];
                __half2 h0 = __floats2half2_rn(f0.x, f0.y);
                __half2 h1 = __floats2half2_rn(f0.z, f0.w);
                __half2 h2 = __floats2half2_rn(f1.x, f1.y);
                __half2 h3 = __floats2half2_rn(f1.z, f1.w);
                o.x = *(unsigned*)&h0; o.y = *(unsigned*)&h1;
                o.z = *(unsigned*)&h2; o.w = *(unsigned*)&h3;
            } else {
                o = make_uint4(0u, 0u, 0u, 0u);
            }
            *(uint4*)(smem + swz((unsigned)r, (unsigned)(c16 * 8))) = o;
        }
    } else {
        const __half* P = (SRC == 1) ? (const __half*)s_P0h : (const __half*)s_P1h;
        #pragma unroll
        for (int it = 0; it < 4; it++) {
            int idx = it * 256 + tid;
            int r   = idx >> 4;
            int c16 = idx & 15;
            int gr  = row0 + r;
            uint4 o = make_uint4(0u, 0u, 0u, 0u);
            if (gr < NN) o = *(const uint4*)(P + (size_t)gr * CC + c16 * 8);
            *(uint4*)(smem + swz((unsigned)r, (unsigned)(c16 * 8))) = o;
        }
    }
    #pragma unroll
    for (int it = 0; it < 8; it++) {
        int idx = it * 256 + tid;
        int r   = idx >> 4;
        int c16 = idx & 15;
        uint4 o = *(const uint4*)(Wh + (size_t)r * CC + c16 * 8);
        *(uint4*)(smem + 16384 + swz((unsigned)r, (unsigned)(c16 * 8))) = o;
    }
    __syncthreads();

    const int warp   = tid >> 5;
    const int lane   = tid & 31;
    const int warp_m = warp & 3;
    const int warp_n = warp >> 2;
    const int rloc   = warp_m * 16;
    const int c0     = warp_n * 64;

    float d[8][4];
    #pragma unroll
    for (int i = 0; i < 8; i++)
        #pragma unroll
        for (int j = 0; j < 4; j++) d[i][j] = 0.f;

    const int fr = (lane & 7) + ((lane >> 3) & 1) * 8;
    const int fc = (lane >> 4) * 8;

    #pragma unroll
    for (int ks = 0; ks < 8; ks++) {
        const int k0 = ks * 16;
        unsigned a0, a1, a2, a3;
        {
            unsigned addrA = sbA + swz((unsigned)(rloc + fr), (unsigned)(k0 + fc));
            asm volatile("ldmatrix.sync.aligned.m8n8.x4.shared.b16 {%0,%1,%2,%3}, [%4];"
                         : "=r"(a0), "=r"(a1), "=r"(a2), "=r"(a3) : "r"(addrA));
        }
        #pragma unroll
        for (int q = 0; q < 4; q++) {
            int n0 = c0 + q * 16;
            unsigned b0, b1, b2, b3;
            unsigned addrB = sbW + swz((unsigned)(k0 + fr), (unsigned)(n0 + fc));
            asm volatile("ldmatrix.sync.aligned.m8n8.x4.trans.shared.b16 {%0,%1,%2,%3}, [%4];"
                         : "=r"(b0), "=r"(b1), "=r"(b2), "=r"(b3) : "r"(addrB));
            asm volatile("mma.sync.aligned.m16n8k16.row.col.f32.f16.f16.f32 "
                         "{%0,%1,%2,%3}, {%4,%5,%6,%7}, {%8,%9}, {%0,%1,%2,%3};"
                         : "+f"(d[q*2][0]), "+f"(d[q*2][1]), "+f"(d[q*2][2]), "+f"(d[q*2][3])
                         : "r"(a0), "r"(a1), "r"(a2), "r"(a3), "r"(b0), "r"(b1));
            asm volatile("mma.sync.aligned.m16n8k16.row.col.f32.f16.f16.f32 "
                         "{%0,%1,%2,%3}, {%4,%5,%6,%7}, {%8,%9}, {%0,%1,%2,%3};"
                         : "+f"(d[q*2+1][0]), "+f"(d[q*2+1][1]), "+f"(d[q*2+1][2]), "+f"(d[q*2+1][3])
                         : "r"(a0), "r"(a1), "r"(a2), "r"(a3), "r"(b2), "r"(b3));
        }
    }

    __half* H = (__half*)s_Hh;
    const int g  = lane >> 2;
    const int cq = (lane & 3) * 2;
    const int ra = row0 + rloc + g;
    const int rb = ra + 8;
    #pragma unroll
    for (int nt = 0; nt < 8; nt++) {
        int col = c0 + nt * 8 + cq;
        if (ra < NN) *(__half2*)(H + (size_t)ra * CC + col) = __floats2half2_rn(d[nt][0], d[nt][1]);
        if (rb < NN) *(__half2*)(H + (size_t)rb * CC + col) = __floats2half2_rn(d[nt][2], d[nt][3]);
    }
}

// ============ aggregation (R9-exact loop): gather fp16, fp32 acc ============
template<int DST>
__global__ void agg_k(const float* __restrict__ b) {
    int node = blockIdx.x * 8 + (threadIdx.x >> 5);
    int lane = threadIdx.x & 31;
    if (node >= NN) return;
    uint2* OUT = (DST == 0) ? s_P0h : s_P1h;

    float di = s_dinv[node];
    float sc = di * di;

    uint2 hs = s_Hh[(size_t)node * 32 + lane];
    float2 h01 = __half22float2(*(__half2*)&hs.x);
    float2 h23 = __half22float2(*(__half2*)&hs.y);
    float4 acc;
    acc.x = fmaf(h01.x, sc, b[lane * 4 + 0]);
    acc.y = fmaf(h01.y, sc, b[lane * 4 + 1]);
    acc.z = fmaf(h23.x, sc, b[lane * 4 + 2]);
    acc.w = fmaf(h23.y, sc, b[lane * 4 + 3]);

    const int beg = s_rowptr[node];
    const int end = s_rowptr[node + 1];
    int e = beg;
    for (; e + 4 <= end; e += 4) {
        int   i0 = s_csrc[e],   i1 = s_csrc[e+1], i2 = s_csrc[e+2], i3 = s_csrc[e+3];
        float c0 = s_coef[e],   c1 = s_coef[e+1], c2 = s_coef[e+2], c3 = s_coef[e+3];
        uint2 r0 = s_Hh[(size_t)i0 * 32 + lane];
        uint2 r1 = s_Hh[(size_t)i1 * 32 + lane];
        uint2 r2 = s_Hh[(size_t)i2 * 32 + lane];
        uint2 r3 = s_Hh[(size_t)i3 * 32 + lane];
        float2 a01, a23;
        a01 = __half22float2(*(__half2*)&r0.x); a23 = __half22float2(*(__half2*)&r0.y);
        acc.x = fmaf(a01.x, c0, acc.x); acc.y = fmaf(a01.y, c0, acc.y);
        acc.z = fmaf(a23.x, c0, acc.z); acc.w = fmaf(a23.y, c0, acc.w);
        a01 = __half22float2(*(__half2*)&r1.x); a23 = __half22float2(*(__half2*)&r1.y);
        acc.x = fmaf(a01.x, c1, acc.x); acc.y = fmaf(a01.y, c1, acc.y);
        acc.z = fmaf(a23.x, c1, acc.z); acc.w = fmaf(a23.y, c1, acc.w);
        a01 = __half22float2(*(__half2*)&r2.x); a23 = __half22float2(*(__half2*)&r2.y);
        acc.x = fmaf(a01.x, c2, acc.x); acc.y = fmaf(a01.y, c2, acc.y);
        acc.z = fmaf(a23.x, c2, acc.z); acc.w = fmaf(a23.y, c2, acc.w);
        a01 = __half22float2(*(__half2*)&r3.x); a23 = __half22float2(*(__half2*)&r3.y);
        acc.x = fmaf(a01.x, c3, acc.x); acc.y = fmaf(a01.y, c3, acc.y);
        acc.z = fmaf(a23.x, c3, acc.z); acc.w = fmaf(a23.y, c3, acc.w);
    }
    for (; e < end; e++) {
        float c0 = s_coef[e];
        uint2 r0 = s_Hh[(size_t)s_csrc[e] * 32 + lane];
        float2 a01 = __half22float2(*(__half2*)&r0.x);
        float2 a23 = __half22float2(*(__half2*)&r0.y);
        acc.x = fmaf(a01.x, c0, acc.x); acc.y = fmaf(a01.y, c0, acc.y);
        acc.z = fmaf(a23.x, c0, acc.z); acc.w = fmaf(a23.y, c0, acc.w);
    }

    __half2 o0 = __floats2half2_rn(fmaxf(acc.x, 0.f), fmaxf(acc.y, 0.f));
    __half2 o1 = __floats2half2_rn(fmaxf(acc.z, 0.f), fmaxf(acc.w, 0.f));
    uint2 o;
    o.x = *(unsigned*)&o0;
    o.y = *(unsigned*)&o1;
    OUT[(size_t)node * 32 + lane] = o;
}

// ============ FINAL aggregation: same gather, epilogue = relu·Wfc dot + pool ============
__global__ void agg_pool_k(const float* __restrict__ b,
                           const float* __restrict__ Wfc,
                           const int* __restrict__ batch) {
    int node = blockIdx.x * 8 + (threadIdx.x >> 5);
    int lane = threadIdx.x & 31;
    if (node >= NN) return;

    float di = s_dinv[node];
    float sc = di * di;

    uint2 hs = s_Hh[(size_t)node * 32 + lane];
    float2 h01 = __half22float2(*(__half2*)&hs.x);
    float2 h23 = __half22float2(*(__half2*)&hs.y);
    float4 acc;
    acc.x = fmaf(h01.x, sc, b[lane * 4 + 0]);
    acc.y = fmaf(h01.y, sc, b[lane * 4 + 1]);
    acc.z = fmaf(h23.x, sc, b[lane * 4 + 2]);
    acc.w = fmaf(h23.y, sc, b[lane * 4 + 3]);

    const int beg = s_rowptr[node];
    const int end = s_rowptr[node + 1];
    int e = beg;
    for (; e + 4 <= end; e += 4) {
        int   i0 = s_csrc[e],   i1 = s_csrc[e+1], i2 = s_csrc[e+2], i3 = s_csrc[e+3];
        float c0 = s_coef[e],   c1 = s_coef[e+1], c2 = s_coef[e+2], c3 = s_coef[e+3];
        uint2 r0 = s_Hh[(size_t)i0 * 32 + lane];
        uint2 r1 = s_Hh[(size_t)i1 * 32 + lane];
        uint2 r2 = s_Hh[(size_t)i2 * 32 + lane];
        uint2 r3 = s_Hh[(size_t)i3 * 32 + lane];
        float2 a01, a23;
        a01 = __half22float2(*(__half2*)&r0.x); a23 = __half22float2(*(__half2*)&r0.y);
        acc.x = fmaf(a01.x, c0, acc.x); acc.y = fmaf(a01.y, c0, acc.y);
        acc.z = fmaf(a23.x, c0, acc.z); acc.w = fmaf(a23.y, c0, acc.w);
        a01 = __half22float2(*(__half2*)&r1.x); a23 = __half22float2(*(__half2*)&r1.y);
        acc.x = fmaf(a01.x, c1, acc.x); acc.y = fmaf(a01.y, c1, acc.y);
        acc.z = fmaf(a23.x, c1, acc.z); acc.w = fmaf(a23.y, c1, acc.w);
        a01 = __half22float2(*(__half2*)&r2.x); a23 = __half22float2(*(__half2*)&r2.y);
        acc.x = fmaf(a01.x, c2, acc.x); acc.y = fmaf(a01.y, c2, acc.y);
        acc.z = fmaf(a23.x, c2, acc.z); acc.w = fmaf(a23.y, c2, acc.w);
        a01 = __half22float2(*(__half2*)&r3.x); a23 = __half22float2(*(__half2*)&r3.y);
        acc.x = fmaf(a01.x, c3, acc.x); acc.y = fmaf(a01.y, c3, acc.y);
        acc.z = fmaf(a23.x, c3, acc.z); acc.w = fmaf(a23.y, c3, acc.w);
    }
    for (; e < end; e++) {
        float c0 = s_coef[e];
        uint2 r0 = s_Hh[(size_t)s_csrc[e] * 32 + lane];
        float2 a01 = __half22float2(*(__half2*)&r0.x);
        float2 a23 = __half22float2(*(__half2*)&r0.y);
        acc.x = fmaf(a01.x, c0, acc.x); acc.y = fmaf(a01.y, c0, acc.y);
        acc.z = fmaf(a23.x, c0, acc.z); acc.w = fmaf(a23.y, c0, acc.w);
    }

    float4 w = *(const float4*)(Wfc + lane * 4);
    float dot = fmaxf(acc.x, 0.f) * w.x + fmaxf(acc.y, 0.f) * w.y
              + fmaxf(acc.z, 0.f) * w.z + fmaxf(acc.w, 0.f) * w.w;
    #pragma unroll
    for (int o = 16; o; o >>= 1) dot += __shfl_xor_sync(0xffffffffu, dot, o);
    if (lane == 0) atomicAdd(&s_gacc[batch[node]], dot);
}

// ============ finalize: out[g] = gacc[g]/cnt(g) + bfc ============
__global__ void final_k(const int* __restrict__ batch,
                        const float* __restrict__ bfc,
                        float* __restrict__ out) {
    int g = threadIdx.x;
    if (g >= NG) return;
    int lo0 = 0, hi0 = NN;
    while (lo0 < hi0) { int m = (lo0 + hi0) >> 1; if (batch[m] < g) lo0 = m + 1; else hi0 = m; }
    int lo1 = lo0, hi1 = NN;
    while (lo1 < hi1) { int m = (lo1 + hi1) >> 1; if (batch[m] < g + 1) lo1 = m + 1; else hi1 = m; }
    float cnt = (float)(lo1 - lo0);
    out[g] = s_gacc[g] / fmaxf(cnt, 1.0f) + bfc[0];
}

extern "C" void kernel_launch(void* const* d_in, const int* in_sizes, int n_in,
                              void* d_out, int out_size) {
    const float* x   = (const float*)d_in[0];
    const int*   ei  = (const int*)d_in[1];    // int32 [2, E]
    const int*   bat = (const int*)d_in[2];    // int32 [N]
    const float* W1  = (const float*)d_in[3];
    const float* b1  = (const float*)d_in[4];
    const float* W2  = (const float*)d_in[5];
    const float* b2  = (const float*)d_in[6];
    const float* Wfc = (const float*)d_in[7];
    const float* bfc = (const float*)d_in[8];
    float*       out = (float*)d_out;

    __half *W1h, *W2h;
    cudaGetSymbolAddress((void**)&W1h, s_W1h);
    cudaGetSymbolAddress((void**)&W2h, s_W2h);

    const int T = 256;
    const int NB_N = (NN + T - 1) / T;
    const int NB_E = (EE + T - 1) / T;
    const int GB   = (NN + 63) / 64;
    const int AB   = (NN + 7) / 8;

    // prologue: fused init -> deg -> fused chained scan -> build
    init_k <<<NB_N, T>>>(W1, W2);
    deg_k  <<<NB_E, T>>>(ei);
    scanf_k<<<NBK, SB>>>();
    build_k<<<NB_E, T>>>(ei);

    // 4 GCN layers; final layer fused with pooling+FC dot
    gemm_tc_k<0><<<GB, 256>>>(x, W1h);  agg_k<0><<<AB, T>>>(b1);             // x   -> P0h
    gemm_tc_k<1><<<GB, 256>>>(x, W2h);  agg_k<1><<<AB, T>>>(b2);             // P0h -> P1h
    gemm_tc_k<2><<<GB, 256>>>(x, W2h);  agg_k<0><<<AB, T>>>(b2);             // P1h -> P0h
    gemm_tc_k<1><<<GB, 256>>>(x, W2h);  agg_pool_k<<<AB, T>>>(b2, Wfc, bat); // P0h -> pooled

    final_k<<<1, NG>>>(bat, bfc, out);
}

// round 15
// speedup vs baseline: 1.2389x; 1.2389x over previous
#include <cuda_runtime.h>
#include <cuda_fp16.h>
#include <cstdint>

#define NN 50000
#define EE 1600000
#define CC 128
#define NG 128
#define SB 1024
#define NBK ((NN + SB - 1) / SB)

// ---- scratch (static device globals) ----
__device__ uint2  s_Hh [NN * 32];    // Hs = (A@W)*dinv, fp16: 128 halves/row
__device__ uint2  s_P0h[NN * 32];    // layer out fp16 (relu applied)
__device__ uint2  s_P1h[NN * 32];
__device__ __half s_W1h[CC * CC];
__device__ __half s_W2h[CC * CC];
__device__ float  s_dinv[NN];
__device__ int    s_deg [NN];
__device__ int    s_rowptr[NN + 1];
__device__ int    s_cursor[NN];
__device__ int    s_csrc [EE];
__device__ int    s_bsum[64];
__device__ int    s_boff[64];
__device__ float  s_gacc[NG];        // pooled dot accumulators

// ============ prologue (R13-identical structure) ============
__global__ void zero_deg_k() {
    int i = blockIdx.x * blockDim.x + threadIdx.x;
    if (i < NN) s_deg[i] = 0;
    if (i < NG) s_gacc[i] = 0.f;
}

__global__ void deg_k(const int* __restrict__ ei) {
    int e = blockIdx.x * blockDim.x + threadIdx.x;
    if (e < EE) {
        int dst = ei[EE + e];
        dst = min(max(dst, 0), NN - 1);
        atomicAdd(&s_deg[dst], 1);
    }
}

__global__ void scan1_k() {
    const int tid  = threadIdx.x;
    const int lane = tid & 31;
    const int wid  = tid >> 5;
    const int i    = blockIdx.x * SB + tid;
    int v = (i < NN) ? s_deg[i] : 0;
    int x = v;
    #pragma unroll
    for (int o = 1; o < 32; o <<= 1) {
        int t = __shfl_up_sync(0xffffffffu, x, o);
        if (lane >= o) x += t;
    }
    __shared__ int wsum[32];
    if (lane == 31) wsum[wid] = x;
    __syncthreads();
    if (wid == 0) {
        int s = wsum[lane];
        #pragma unroll
        for (int o = 1; o < 32; o <<= 1) {
            int t = __shfl_up_sync(0xffffffffu, s, o);
            if (lane >= o) s += t;
        }
        wsum[lane] = s;
    }
    __syncthreads();
    int incl = x + (wid ? wsum[wid - 1] : 0);
    if (i < NN) s_rowptr[i] = incl - v;
    if (tid == SB - 1) s_bsum[blockIdx.x] = incl;
}

__global__ void scan2_k() {
    __shared__ int sh[64];
    int t = threadIdx.x;
    int v = (t < NBK) ? s_bsum[t] : 0;
    sh[t] = v;
    __syncthreads();
    for (int o = 1; o < 64; o <<= 1) {
        int u = (t >= o) ? sh[t - o] : 0;
        __syncthreads();
        sh[t] += u;
        __syncthreads();
    }
    s_boff[t] = sh[t] - v;
}

__global__ void scan3_k() {
    int i = blockIdx.x * SB + threadIdx.x;
    if (i < NN) {
        int ex = s_rowptr[i] + s_boff[blockIdx.x];
        s_rowptr[i] = ex;
        s_cursor[i] = ex;
        s_dinv[i]   = rsqrtf((float)s_deg[i] + 1.0f);
    }
    if (i == 0) s_rowptr[NN] = EE;
}

// counting-sort by dst — NO dinv gathers, NO coef store (src only)
__global__ void build_k(const int* __restrict__ ei) {
    int e = blockIdx.x * blockDim.x + threadIdx.x;
    if (e >= EE) return;
    int src = ei[e];
    int dst = ei[EE + e];
    src = min(max(src, 0), NN - 1);
    dst = min(max(dst, 0), NN - 1);
    int slot = atomicAdd(&s_cursor[dst], 1);
    s_csrc[slot] = src;
}

// convert both weight matrices to fp16 once
__global__ void wconv_k(const float* __restrict__ W1, const float* __restrict__ W2) {
    int i = blockIdx.x * blockDim.x + threadIdx.x;
    if (i < CC * CC) {
        s_W1h[i] = __float2half(W1[i]);
        s_W2h[i] = __float2half(W2[i]);
    }
}

// ============ tensor-core GEMM: Hs(fp16) = (A @ W) * dinv[row] ============
__device__ __forceinline__ unsigned swz(unsigned row, unsigned col_half) {
    unsigned b = row * 256u + col_half * 2u;
    return b ^ ((row & 7u) << 4);
}

template<int SRC>
__global__ void __launch_bounds__(256) gemm_tc_k(const float* __restrict__ X,
                                                 const __half* __restrict__ Wh) {
    __shared__ __align__(16) unsigned char smem[49152];   // A: 16KB, W: 32KB
    const unsigned sb  = (unsigned)__cvta_generic_to_shared(smem);
    const unsigned sbA = sb;
    const unsigned sbW = sb + 16384u;
    const int tid  = threadIdx.x;
    const int row0 = blockIdx.x * 64;

    if (SRC == 0) {
        #pragma unroll
        for (int it = 0; it < 4; it++) {
            int idx = it * 256 + tid;
            int r   = idx >> 4;
            int c16 = idx & 15;
            int gr  = row0 + r;
            uint4 o;
            if (gr < NN) {
                const float4* p = (const float4*)(X + (size_t)gr * CC + c16 * 8);
                float4 f0 = p[0], f1 = p[1];
                __half2 h0 = __floats2half2_rn(f0.x, f0.y);
                __half2 h1 = __floats2half2_rn(f0.z, f0.w);
                __half2 h2 = __floats2half2_rn(f1.x, f1.y);
                __half2 h3 = __floats2half2_rn(f1.z, f1.w);
                o.x = *(unsigned*)&h0; o.y = *(unsigned*)&h1;
                o.z = *(unsigned*)&h2; o.w = *(unsigned*)&h3;
            } else {
                o = make_uint4(0u, 0u, 0u, 0u);
            }
            *(uint4*)(smem + swz((unsigned)r, (unsigned)(c16 * 8))) = o;
        }
    } else {
        const __half* P = (SRC == 1) ? (const __half*)s_P0h : (const __half*)s_P1h;
        #pragma unroll
        for (int it = 0; it < 4; it++) {
            int idx = it * 256 + tid;
            int r   = idx >> 4;
            int c16 = idx & 15;
            int gr  = row0 + r;
            uint4 o = make_uint4(0u, 0u, 0u, 0u);
            if (gr < NN) o = *(const uint4*)(P + (size_t)gr * CC + c16 * 8);
            *(uint4*)(smem + swz((unsigned)r, (unsigned)(c16 * 8))) = o;
        }
    }
    #pragma unroll
    for (int it = 0; it < 8; it++) {
        int idx = it * 256 + tid;
        int r   = idx >> 4;
        int c16 = idx & 15;
        uint4 o = *(const uint4*)(Wh + (size_t)r * CC + c16 * 8);
        *(uint4*)(smem + 16384 + swz((unsigned)r, (unsigned)(c16 * 8))) = o;
    }
    __syncthreads();

    const int warp   = tid >> 5;
    const int lane   = tid & 31;
    const int warp_m = warp & 3;
    const int warp_n = warp >> 2;
    const int rloc   = warp_m * 16;
    const int c0     = warp_n * 64;

    float d[8][4];
    #pragma unroll
    for (int i = 0; i < 8; i++)
        #pragma unroll
        for (int j = 0; j < 4; j++) d[i][j] = 0.f;

    const int fr = (lane & 7) + ((lane >> 3) & 1) * 8;
    const int fc = (lane >> 4) * 8;

    #pragma unroll
    for (int ks = 0; ks < 8; ks++) {
        const int k0 = ks * 16;
        unsigned a0, a1, a2, a3;
        {
            unsigned addrA = sbA + swz((unsigned)(rloc + fr), (unsigned)(k0 + fc));
            asm volatile("ldmatrix.sync.aligned.m8n8.x4.shared.b16 {%0,%1,%2,%3}, [%4];"
                         : "=r"(a0), "=r"(a1), "=r"(a2), "=r"(a3) : "r"(addrA));
        }
        #pragma unroll
        for (int q = 0; q < 4; q++) {
            int n0 = c0 + q * 16;
            unsigned b0, b1, b2, b3;
            unsigned addrB = sbW + swz((unsigned)(k0 + fr), (unsigned)(n0 + fc));
            asm volatile("ldmatrix.sync.aligned.m8n8.x4.trans.shared.b16 {%0,%1,%2,%3}, [%4];"
                         : "=r"(b0), "=r"(b1), "=r"(b2), "=r"(b3) : "r"(addrB));
            asm volatile("mma.sync.aligned.m16n8k16.row.col.f32.f16.f16.f32 "
                         "{%0,%1,%2,%3}, {%4,%5,%6,%7}, {%8,%9}, {%0,%1,%2,%3};"
                         : "+f"(d[q*2][0]), "+f"(d[q*2][1]), "+f"(d[q*2][2]), "+f"(d[q*2][3])
                         : "r"(a0), "r"(a1), "r"(a2), "r"(a3), "r"(b0), "r"(b1));
            asm volatile("mma.sync.aligned.m16n8k16.row.col.f32.f16.f16.f32 "
                         "{%0,%1,%2,%3}, {%4,%5,%6,%7}, {%8,%9}, {%0,%1,%2,%3};"
                         : "+f"(d[q*2+1][0]), "+f"(d[q*2+1][1]), "+f"(d[q*2+1][2]), "+f"(d[q*2+1][3])
                         : "r"(a0), "r"(a1), "r"(a2), "r"(a3), "r"(b2), "r"(b3));
        }
    }

    // epilogue: scale by dinv[row], write Hs fp16
    __half* H = (__half*)s_Hh;
    const int g  = lane >> 2;
    const int cq = (lane & 3) * 2;
    const int ra = row0 + rloc + g;
    const int rb = ra + 8;
    const float da = (ra < NN) ? s_dinv[ra] : 0.f;
    const float db = (rb < NN) ? s_dinv[rb] : 0.f;
    #pragma unroll
    for (int nt = 0; nt < 8; nt++) {
        int col = c0 + nt * 8 + cq;
        if (ra < NN) *(__half2*)(H + (size_t)ra * CC + col) =
            __floats2half2_rn(d[nt][0] * da, d[nt][1] * da);
        if (rb < NN) *(__half2*)(H + (size_t)rb * CC + col) =
            __floats2half2_rn(d[nt][2] * db, d[nt][3] * db);
    }
}

// shared gather: sum = Hs[node] + sum_e Hs[src_e]  (pure adds, no coef)
__device__ __forceinline__ float4 gather_sum(int node, int lane) {
    uint2 hs = s_Hh[(size_t)node * 32 + lane];
    float2 h01 = __half22float2(*(__half2*)&hs.x);
    float2 h23 = __half22float2(*(__half2*)&hs.y);
    float4 acc = make_float4(h01.x, h01.y, h23.x, h23.y);

    const int beg = s_rowptr[node];
    const int end = s_rowptr[node + 1];
    int e = beg;
    for (; e + 4 <= end; e += 4) {
        int i0 = s_csrc[e], i1 = s_csrc[e+1], i2 = s_csrc[e+2], i3 = s_csrc[e+3];
        uint2 r0 = s_Hh[(size_t)i0 * 32 + lane];
        uint2 r1 = s_Hh[(size_t)i1 * 32 + lane];
        uint2 r2 = s_Hh[(size_t)i2 * 32 + lane];
        uint2 r3 = s_Hh[(size_t)i3 * 32 + lane];
        float2 a01, a23;
        a01 = __half22float2(*(__half2*)&r0.x); a23 = __half22float2(*(__half2*)&r0.y);
        acc.x += a01.x; acc.y += a01.y; acc.z += a23.x; acc.w += a23.y;
        a01 = __half22float2(*(__half2*)&r1.x); a23 = __half22float2(*(__half2*)&r1.y);
        acc.x += a01.x; acc.y += a01.y; acc.z += a23.x; acc.w += a23.y;
        a01 = __half22float2(*(__half2*)&r2.x); a23 = __half22float2(*(__half2*)&r2.y);
        acc.x += a01.x; acc.y += a01.y; acc.z += a23.x; acc.w += a23.y;
        a01 = __half22float2(*(__half2*)&r3.x); a23 = __half22float2(*(__half2*)&r3.y);
        acc.x += a01.x; acc.y += a01.y; acc.z += a23.x; acc.w += a23.y;
    }
    for (; e < end; e++) {
        uint2 r0 = s_Hh[(size_t)s_csrc[e] * 32 + lane];
        float2 a01 = __half22float2(*(__half2*)&r0.x);
        float2 a23 = __half22float2(*(__half2*)&r0.y);
        acc.x += a01.x; acc.y += a01.y; acc.z += a23.x; acc.w += a23.y;
    }
    return acc;
}

// ============ mid-layer aggregation: out = relu(sum*dinv + b), fp16 ============
template<int DST>
__global__ void agg_k(const float* __restrict__ b) {
    int node = blockIdx.x * 8 + (threadIdx.x >> 5);
    int lane = threadIdx.x & 31;
    if (node >= NN) return;
    uint2* OUT = (DST == 0) ? s_P0h : s_P1h;

    float4 sum = gather_sum(node, lane);
    float di = s_dinv[node];
    float vx = fmaf(sum.x, di, b[lane * 4 + 0]);
    float vy = fmaf(sum.y, di, b[lane * 4 + 1]);
    float vz = fmaf(sum.z, di, b[lane * 4 + 2]);
    float vw = fmaf(sum.w, di, b[lane * 4 + 3]);

    __half2 o0 = __floats2half2_rn(fmaxf(vx, 0.f), fmaxf(vy, 0.f));
    __half2 o1 = __floats2half2_rn(fmaxf(vz, 0.f), fmaxf(vw, 0.f));
    uint2 o;
    o.x = *(unsigned*)&o0;
    o.y = *(unsigned*)&o1;
    OUT[(size_t)node * 32 + lane] = o;
}

// ============ FINAL aggregation: relu -> dot(Wfc) -> pool atomic ============
__global__ void agg_pool_k(const float* __restrict__ b,
                           const float* __restrict__ Wfc,
                           const int* __restrict__ batch) {
    int node = blockIdx.x * 8 + (threadIdx.x >> 5);
    int lane = threadIdx.x & 31;
    if (node >= NN) return;

    float4 sum = gather_sum(node, lane);
    float di = s_dinv[node];
    float vx = fmaf(sum.x, di, b[lane * 4 + 0]);
    float vy = fmaf(sum.y, di, b[lane * 4 + 1]);
    float vz = fmaf(sum.z, di, b[lane * 4 + 2]);
    float vw = fmaf(sum.w, di, b[lane * 4 + 3]);

    float4 w = *(const float4*)(Wfc + lane * 4);
    float dot = fmaxf(vx, 0.f) * w.x + fmaxf(vy, 0.f) * w.y
              + fmaxf(vz, 0.f) * w.z + fmaxf(vw, 0.f) * w.w;
    #pragma unroll
    for (int o = 16; o; o >>= 1) dot += __shfl_xor_sync(0xffffffffu, dot, o);
    if (lane == 0) atomicAdd(&s_gacc[batch[node]], dot);
}

// ============ finalize: out[g] = gacc[g]/cnt(g) + bfc ============
__global__ void final_k(const int* __restrict__ batch,
                        const float* __restrict__ bfc,
                        float* __restrict__ out) {
    int g = threadIdx.x;
    if (g >= NG) return;
    int lo0 = 0, hi0 = NN;
    while (lo0 < hi0) { int m = (lo0 + hi0) >> 1; if (batch[m] < g) lo0 = m + 1; else hi0 = m; }
    int lo1 = lo0, hi1 = NN;
    while (lo1 < hi1) { int m = (lo1 + hi1) >> 1; if (batch[m] < g + 1) lo1 = m + 1; else hi1 = m; }
    float cnt = (float)(lo1 - lo0);
    out[g] = s_gacc[g] / fmaxf(cnt, 1.0f) + bfc[0];
}

extern "C" void kernel_launch(void* const* d_in, const int* in_sizes, int n_in,
                              void* d_out, int out_size) {
    const float* x   = (const float*)d_in[0];
    const int*   ei  = (const int*)d_in[1];    // int32 [2, E]
    const int*   bat = (const int*)d_in[2];    // int32 [N]
    const float* W1  = (const float*)d_in[3];
    const float* b1  = (const float*)d_in[4];
    const float* W2  = (const float*)d_in[5];
    const float* b2  = (const float*)d_in[6];
    const float* Wfc = (const float*)d_in[7];
    const float* bfc = (const float*)d_in[8];
    float*       out = (float*)d_out;

    __half *W1h, *W2h;
    cudaGetSymbolAddress((void**)&W1h, s_W1h);
    cudaGetSymbolAddress((void**)&W2h, s_W2h);

    const int T = 256;
    const int NB_N = (NN + T - 1) / T;
    const int NB_E = (EE + T - 1) / T;
    const int GB   = (NN + 63) / 64;
    const int AB   = (NN + 7) / 8;

    // prologue: CSR build (3-phase scan, R13-proven) — build no longer gathers dinv
    zero_deg_k<<<NB_N, T>>>();
    deg_k     <<<NB_E, T>>>(ei);
    scan1_k   <<<NBK, SB>>>();
    scan2_k   <<<1, 64>>>();
    scan3_k   <<<NBK, SB>>>();
    build_k   <<<NB_E, T>>>(ei);
    wconv_k   <<<(CC * CC + T - 1) / T, T>>>(W1, W2);

    // 4 GCN layers; final layer fused with pooling+FC dot
    gemm_tc_k<0><<<GB, 256>>>(x, W1h);  agg_k<0><<<AB, T>>>(b1);             // x   -> P0h
    gemm_tc_k<1><<<GB, 256>>>(x, W2h);  agg_k<1><<<AB, T>>>(b2);             // P0h -> P1h
    gemm_tc_k<2><<<GB, 256>>>(x, W2h);  agg_k<0><<<AB, T>>>(b2);             // P1h -> P0h
    gemm_tc_k<1><<<GB, 256>>>(x, W2h);  agg_pool_k<<<AB, T>>>(b2, Wfc, bat); // P0h -> pooled

    final_k<<<1, NG>>>(bat, bfc, out);
}

// round 16
// speedup vs baseline: 1.2455x; 1.0053x over previous
#include <cuda_runtime.h>
#include <cuda_fp16.h>
#include <cstdint>

#define NN 50000
#define EE 1600000
#define CC 128
#define NG 128
#define SB 1024
#define NBK ((NN + SB - 1) / SB)   // 49

// ---- scratch (static device globals) ----
__device__ uint2  s_Hh [NN * 32];    // Hs = (A@W)*dinv, fp16: 128 halves/row
__device__ uint2  s_P0h[NN * 32];    // layer out fp16 (relu applied)
__device__ uint2  s_P1h[NN * 32];
__device__ __half s_W1h[CC * CC];
__device__ __half s_W2h[CC * CC];
__device__ float  s_dinv[NN];
__device__ int    s_deg [NN];
__device__ int    s_rowptr[NN + 1];
__device__ int    s_cursor[NN];
__device__ int    s_csrc [EE];
__device__ int    s_bsum[64];
__device__ float  s_gacc[NG];        // pooled dot accumulators

// ============ init: zero deg/gacc + convert W (one kernel) ============
__global__ void init_k(const float* __restrict__ W1, const float* __restrict__ W2) {
    int i = blockIdx.x * blockDim.x + threadIdx.x;
    if (i < NN) s_deg[i] = 0;
    if (i < NG) s_gacc[i] = 0.f;
    if (i < CC * CC) {
        s_W1h[i] = __float2half(W1[i]);
        s_W2h[i] = __float2half(W2[i]);
    }
}

// degree of dst (2 edges per thread, int2 load)
__global__ void deg_k(const int* __restrict__ ei) {
    int t = blockIdx.x * blockDim.x + threadIdx.x;
    int e = t * 2;
    if (e + 1 < EE) {
        int2 d2 = *(const int2*)(ei + EE + e);
        int d0 = min(max(d2.x, 0), NN - 1);
        int d1 = min(max(d2.y, 0), NN - 1);
        atomicAdd(&s_deg[d0], 1);
        atomicAdd(&s_deg[d1], 1);
    } else if (e < EE) {
        int d0 = min(max(ei[EE + e], 0), NN - 1);
        atomicAdd(&s_deg[d0], 1);
    }
}

// scan phase 1: per-block inclusive scan; block-exclusive into rowptr, totals to bsum
__global__ void scan1_k() {
    const int tid  = threadIdx.x;
    const int lane = tid & 31;
    const int wid  = tid >> 5;
    const int i    = blockIdx.x * SB + tid;
    int v = (i < NN) ? s_deg[i] : 0;
    int x = v;
    #pragma unroll
    for (int o = 1; o < 32; o <<= 1) {
        int t = __shfl_up_sync(0xffffffffu, x, o);
        if (lane >= o) x += t;
    }
    __shared__ int wsum[32];
    if (lane == 31) wsum[wid] = x;
    __syncthreads();
    if (wid == 0) {
        int s = wsum[lane];
        #pragma unroll
        for (int o = 1; o < 32; o <<= 1) {
            int t = __shfl_up_sync(0xffffffffu, s, o);
            if (lane >= o) s += t;
        }
        wsum[lane] = s;
    }
    __syncthreads();
    int incl = x + (wid ? wsum[wid - 1] : 0);
    if (i < NN) s_rowptr[i] = incl - v;
    if (tid == SB - 1) s_bsum[blockIdx.x] = incl;
}

// scan phase 2+3 fused: each block computes its own offset from bsum, applies,
// inits cursor + dinv + sentinel.
__global__ void scan3_k() {
    const int tid = threadIdx.x;
    const int bid = blockIdx.x;
    __shared__ int sbase;
    if (tid < 32) {
        // sum of s_bsum[0..bid) — bid <= 48, two 32-wide strips
        int v = 0;
        if (tid < bid) v = s_bsum[tid];
        if (tid + 32 < bid) v += s_bsum[tid + 32];
        #pragma unroll
        for (int o = 16; o; o >>= 1) v += __shfl_xor_sync(0xffffffffu, v, o);
        if (tid == 0) sbase = v;
    }
    __syncthreads();
    int base = sbase;
    int i = bid * SB + tid;
    if (i < NN) {
        int ex = s_rowptr[i] + base;
        s_rowptr[i] = ex;
        s_cursor[i] = ex;
        s_dinv[i]   = rsqrtf((float)s_deg[i] + 1.0f);
    }
    if (i == 0) s_rowptr[NN] = EE;
}

// counting-sort by dst — src only (no dinv/coef; pre-scaled messages)
__global__ void build_k(const int* __restrict__ ei) {
    int e = blockIdx.x * blockDim.x + threadIdx.x;
    if (e >= EE) return;
    int src = ei[e];
    int dst = ei[EE + e];
    src = min(max(src, 0), NN - 1);
    dst = min(max(dst, 0), NN - 1);
    int slot = atomicAdd(&s_cursor[dst], 1);
    s_csrc[slot] = src;
}

// ============ tensor-core GEMM: Hs(fp16) = (A @ W) * dinv[row] ============
__device__ __forceinline__ unsigned swz(unsigned row, unsigned col_half) {
    unsigned b = row * 256u + col_half * 2u;
    return b ^ ((row & 7u) << 4);
}

template<int SRC>
__global__ void __launch_bounds__(256) gemm_tc_k(const float* __restrict__ X,
                                                 const __half* __restrict__ Wh) {
    __shared__ __align__(16) unsigned char smem[49152];   // A: 16KB, W: 32KB
    const unsigned sb  = (unsigned)__cvta_generic_to_shared(smem);
    const unsigned sbA = sb;
    const unsigned sbW = sb + 16384u;
    const int tid  = threadIdx.x;
    const int row0 = blockIdx.x * 64;

    if (SRC == 0) {
        #pragma unroll
        for (int it = 0; it < 4; it++) {
            int idx = it * 256 + tid;
            int r   = idx >> 4;
            int c16 = idx & 15;
            int gr  = row0 + r;
            uint4 o;
            if (gr < NN) {
                const float4* p = (const float4*)(X + (size_t)gr * CC + c16 * 8);
                float4 f0 = p[0], f1 = p[1];
                __half2 h0 = __floats2half2_rn(f0.x, f0.y);
                __half2 h1 = __floats2half2_rn(f0.z, f0.w);
                __half2 h2 = __floats2half2_rn(f1.x, f1.y);
                __half2 h3 = __floats2half2_rn(f1.z, f1.w);
                o.x = *(unsigned*)&h0; o.y = *(unsigned*)&h1;
                o.z = *(unsigned*)&h2; o.w = *(unsigned*)&h3;
            } else {
                o = make_uint4(0u, 0u, 0u, 0u);
            }
            *(uint4*)(smem + swz((unsigned)r, (unsigned)(c16 * 8))) = o;
        }
    } else {
        const __half* P = (SRC == 1) ? (const __half*)s_P0h : (const __half*)s_P1h;
        #pragma unroll
        for (int it = 0; it < 4; it++) {
            int idx = it * 256 + tid;
            int r   = idx >> 4;
            int c16 = idx & 15;
            int gr  = row0 + r;
            uint4 o = make_uint4(0u, 0u, 0u, 0u);
            if (gr < NN) o = *(const uint4*)(P + (size_t)gr * CC + c16 * 8);
            *(uint4*)(smem + swz((unsigned)r, (unsigned)(c16 * 8))) = o;
        }
    }
    #pragma unroll
    for (int it = 0; it < 8; it++) {
        int idx = it * 256 + tid;
        int r   = idx >> 4;
        int c16 = idx & 15;
        uint4 o = *(const uint4*)(Wh + (size_t)r * CC + c16 * 8);
        *(uint4*)(smem + 16384 + swz((unsigned)r, (unsigned)(c16 * 8))) = o;
    }
    __syncthreads();

    const int warp   = tid >> 5;
    const int lane   = tid & 31;
    const int warp_m = warp & 3;
    const int warp_n = warp >> 2;
    const int rloc   = warp_m * 16;
    const int c0     = warp_n * 64;

    float d[8][4];
    #pragma unroll
    for (int i = 0; i < 8; i++)
        #pragma unroll
        for (int j = 0; j < 4; j++) d[i][j] = 0.f;

    const int fr = (lane & 7) + ((lane >> 3) & 1) * 8;
    const int fc = (lane >> 4) * 8;

    #pragma unroll
    for (int ks = 0; ks < 8; ks++) {
        const int k0 = ks * 16;
        unsigned a0, a1, a2, a3;
        {
            unsigned addrA = sbA + swz((unsigned)(rloc + fr), (unsigned)(k0 + fc));
            asm volatile("ldmatrix.sync.aligned.m8n8.x4.shared.b16 {%0,%1,%2,%3}, [%4];"
                         : "=r"(a0), "=r"(a1), "=r"(a2), "=r"(a3) : "r"(addrA));
        }
        #pragma unroll
        for (int q = 0; q < 4; q++) {
            int n0 = c0 + q * 16;
            unsigned b0, b1, b2, b3;
            unsigned addrB = sbW + swz((unsigned)(k0 + fr), (unsigned)(n0 + fc));
            asm volatile("ldmatrix.sync.aligned.m8n8.x4.trans.shared.b16 {%0,%1,%2,%3}, [%4];"
                         : "=r"(b0), "=r"(b1), "=r"(b2), "=r"(b3) : "r"(addrB));
            asm volatile("mma.sync.aligned.m16n8k16.row.col.f32.f16.f16.f32 "
                         "{%0,%1,%2,%3}, {%4,%5,%6,%7}, {%8,%9}, {%0,%1,%2,%3};"
                         : "+f"(d[q*2][0]), "+f"(d[q*2][1]), "+f"(d[q*2][2]), "+f"(d[q*2][3])
                         : "r"(a0), "r"(a1), "r"(a2), "r"(a3), "r"(b0), "r"(b1));
            asm volatile("mma.sync.aligned.m16n8k16.row.col.f32.f16.f16.f32 "
                         "{%0,%1,%2,%3}, {%4,%5,%6,%7}, {%8,%9}, {%0,%1,%2,%3};"
                         : "+f"(d[q*2+1][0]), "+f"(d[q*2+1][1]), "+f"(d[q*2+1][2]), "+f"(d[q*2+1][3])
                         : "r"(a0), "r"(a1), "r"(a2), "r"(a3), "r"(b2), "r"(b3));
        }
    }

    // epilogue: scale by dinv[row], write Hs fp16
    __half* H = (__half*)s_Hh;
    const int g  = lane >> 2;
    const int cq = (lane & 3) * 2;
    const int ra = row0 + rloc + g;
    const int rb = ra + 8;
    const float da = (ra < NN) ? s_dinv[ra] : 0.f;
    const float db = (rb < NN) ? s_dinv[rb] : 0.f;
    #pragma unroll
    for (int nt = 0; nt < 8; nt++) {
        int col = c0 + nt * 8 + cq;
        if (ra < NN) *(__half2*)(H + (size_t)ra * CC + col) =
            __floats2half2_rn(d[nt][0] * da, d[nt][1] * da);
        if (rb < NN) *(__half2*)(H + (size_t)rb * CC + col) =
            __floats2half2_rn(d[nt][2] * db, d[nt][3] * db);
    }
}

// shared gather: sum = Hs[node] + sum_e Hs[src_e]  (pure adds)
__device__ __forceinline__ float4 gather_sum(int node, int lane) {
    uint2 hs = s_Hh[(size_t)node * 32 + lane];
    float2 h01 = __half22float2(*(__half2*)&hs.x);
    float2 h23 = __half22float2(*(__half2*)&hs.y);
    float4 acc = make_float4(h01.x, h01.y, h23.x, h23.y);

    const int beg = s_rowptr[node];
    const int end = s_rowptr[node + 1];
    int e = beg;
    for (; e + 4 <= end; e += 4) {
        int i0 = s_csrc[e], i1 = s_csrc[e+1], i2 = s_csrc[e+2], i3 = s_csrc[e+3];
        uint2 r0 = s_Hh[(size_t)i0 * 32 + lane];
        uint2 r1 = s_Hh[(size_t)i1 * 32 + lane];
        uint2 r2 = s_Hh[(size_t)i2 * 32 + lane];
        uint2 r3 = s_Hh[(size_t)i3 * 32 + lane];
        float2 a01, a23;
        a01 = __half22float2(*(__half2*)&r0.x); a23 = __half22float2(*(__half2*)&r0.y);
        acc.x += a01.x; acc.y += a01.y; acc.z += a23.x; acc.w += a23.y;
        a01 = __half22float2(*(__half2*)&r1.x); a23 = __half22float2(*(__half2*)&r1.y);
        acc.x += a01.x; acc.y += a01.y; acc.z += a23.x; acc.w += a23.y;
        a01 = __half22float2(*(__half2*)&r2.x); a23 = __half22float2(*(__half2*)&r2.y);
        acc.x += a01.x; acc.y += a01.y; acc.z += a23.x; acc.w += a23.y;
        a01 = __half22float2(*(__half2*)&r3.x); a23 = __half22float2(*(__half2*)&r3.y);
        acc.x += a01.x; acc.y += a01.y; acc.z += a23.x; acc.w += a23.y;
    }
    for (; e < end; e++) {
        uint2 r0 = s_Hh[(size_t)s_csrc[e] * 32 + lane];
        float2 a01 = __half22float2(*(__half2*)&r0.x);
        float2 a23 = __half22float2(*(__half2*)&r0.y);
        acc.x += a01.x; acc.y += a01.y; acc.z += a23.x; acc.w += a23.y;
    }
    return acc;
}

// ============ mid-layer aggregation: out = relu(sum*dinv + b), fp16 ============
template<int DST>
__global__ void agg_k(const float* __restrict__ b) {
    int node = blockIdx.x * 8 + (threadIdx.x >> 5);
    int lane = threadIdx.x & 31;
    if (node >= NN) return;
    uint2* OUT = (DST == 0) ? s_P0h : s_P1h;

    float4 sum = gather_sum(node, lane);
    float di = s_dinv[node];
    float vx = fmaf(sum.x, di, b[lane * 4 + 0]);
    float vy = fmaf(sum.y, di, b[lane * 4 + 1]);
    float vz = fmaf(sum.z, di, b[lane * 4 + 2]);
    float vw = fmaf(sum.w, di, b[lane * 4 + 3]);

    __half2 o0 = __floats2half2_rn(fmaxf(vx, 0.f), fmaxf(vy, 0.f));
    __half2 o1 = __floats2half2_rn(fmaxf(vz, 0.f), fmaxf(vw, 0.f));
    uint2 o;
    o.x = *(unsigned*)&o0;
    o.y = *(unsigned*)&o1;
    OUT[(size_t)node * 32 + lane] = o;
}

// ============ FINAL aggregation: relu -> dot(Wfc) -> pool atomic ============
__global__ void agg_pool_k(const float* __restrict__ b,
                           const float* __restrict__ Wfc,
                           const int* __restrict__ batch) {
    int node = blockIdx.x * 8 + (threadIdx.x >> 5);
    int lane = threadIdx.x & 31;
    if (node >= NN) return;

    float4 sum = gather_sum(node, lane);
    float di = s_dinv[node];
    float vx = fmaf(sum.x, di, b[lane * 4 + 0]);
    float vy = fmaf(sum.y, di, b[lane * 4 + 1]);
    float vz = fmaf(sum.z, di, b[lane * 4 + 2]);
    float vw = fmaf(sum.w, di, b[lane * 4 + 3]);

    float4 w = *(const float4*)(Wfc + lane * 4);
    float dot = fmaxf(vx, 0.f) * w.x + fmaxf(vy, 0.f) * w.y
              + fmaxf(vz, 0.f) * w.z + fmaxf(vw, 0.f) * w.w;
    #pragma unroll
    for (int o = 16; o; o >>= 1) dot += __shfl_xor_sync(0xffffffffu, dot, o);
    if (lane == 0) atomicAdd(&s_gacc[batch[node]], dot);
}

// ============ finalize: out[g] = gacc[g]/cnt(g) + bfc ============
__global__ void final_k(const int* __restrict__ batch,
                        const float* __restrict__ bfc,
                        float* __restrict__ out) {
    int g = threadIdx.x;
    if (g >= NG) return;
    int lo0 = 0, hi0 = NN;
    while (lo0 < hi0) { int m = (lo0 + hi0) >> 1; if (batch[m] < g) lo0 = m + 1; else hi0 = m; }
    int lo1 = lo0, hi1 = NN;
    while (lo1 < hi1) { int m = (lo1 + hi1) >> 1; if (batch[m] < g + 1) lo1 = m + 1; else hi1 = m; }
    float cnt = (float)(lo1 - lo0);
    out[g] = s_gacc[g] / fmaxf(cnt, 1.0f) + bfc[0];
}

extern "C" void kernel_launch(void* const* d_in, const int* in_sizes, int n_in,
                              void* d_out, int out_size) {
    const float* x   = (const float*)d_in[0];
    const int*   ei  = (const int*)d_in[1];    // int32 [2, E]
    const int*   bat = (const int*)d_in[2];    // int32 [N]
    const float* W1  = (const float*)d_in[3];
    const float* b1  = (const float*)d_in[4];
    const float* W2  = (const float*)d_in[5];
    const float* b2  = (const float*)d_in[6];
    const float* Wfc = (const float*)d_in[7];
    const float* bfc = (const float*)d_in[8];
    float*       out = (float*)d_out;

    __half *W1h, *W2h;
    cudaGetSymbolAddress((void**)&W1h, s_W1h);
    cudaGetSymbolAddress((void**)&W2h, s_W2h);

    const int T = 256;
    const int NB_N = (NN + T - 1) / T;
    const int NB_E = (EE + T - 1) / T;
    const int NB_E2 = (EE / 2 + T - 1) / T;
    const int GB   = (NN + 63) / 64;
    const int AB   = (NN + 7) / 8;

    // prologue: init(zero+wconv) -> deg(x2) -> scan1 -> scan(2+3 fused) -> build
    init_k <<<NB_N, T>>>(W1, W2);
    deg_k  <<<NB_E2, T>>>(ei);
    scan1_k<<<NBK, SB>>>();
    scan3_k<<<NBK, SB>>>();
    build_k<<<NB_E, T>>>(ei);

    // 4 GCN layers; final layer fused with pooling+FC dot
    gemm_tc_k<0><<<GB, 256>>>(x, W1h);  agg_k<0><<<AB, T>>>(b1);             // x   -> P0h
    gemm_tc_k<1><<<GB, 256>>>(x, W2h);  agg_k<1><<<AB, T>>>(b2);             // P0h -> P1h
    gemm_tc_k<2><<<GB, 256>>>(x, W2h);  agg_k<0><<<AB, T>>>(b2);             // P1h -> P0h
    gemm_tc_k<1><<<GB, 256>>>(x, W2h);  agg_pool_k<<<AB, T>>>(b2, Wfc, bat); // P0h -> pooled

    final_k<<<1, NG>>>(bat, bfc, out);
}